// round 2
// baseline (speedup 1.0000x reference)
#include <cuda_runtime.h>
#include <cuda_bf16.h>
#include <cstdint>

// Problem constants (reference: N=100000, E=1600000, IN=HID=128, OUT=64)
#define NMAX 100000
#define FIN  128
#define FHID 128
#define FOUT 64

// Scratch: device globals (no allocation allowed)
__device__ float g_dinv[NMAX];               // degree -> rsqrt(degree)
__device__ float g_Hs [(size_t)NMAX * FHID]; // (X@W1) * dinv[row]
__device__ float g_A  [(size_t)NMAX * FHID]; // layer-1 aggregate accumulator
__device__ float g_Hs2[(size_t)NMAX * FOUT]; // (H2@W2) * dinv[row]
__device__ float g_A2 [(size_t)NMAX * FOUT]; // layer-2 aggregate accumulator

// ---------------------------------------------------------------------------
// Degree / normalization
// ---------------------------------------------------------------------------
__global__ void k_init_dinv(int N) {
    int i = blockIdx.x * blockDim.x + threadIdx.x;
    if (i < N) g_dinv[i] = 1.0f;  // self-loop contributes 1 to every degree
}

__global__ void k_count_deg(const int* __restrict__ col, int E) {
    int e = blockIdx.x * blockDim.x + threadIdx.x;
    if (e < E) atomicAdd(&g_dinv[col[e]], 1.0f);
}

__global__ void k_finish_dinv(int N) {
    int i = blockIdx.x * blockDim.x + threadIdx.x;
    if (i < N) g_dinv[i] = rsqrtf(g_dinv[i]);
}

// ---------------------------------------------------------------------------
// GEMM1: Hs = (X @ W1) * dinv[row];  A initialized to Hs (self-loop term).
// BM=128, BN=128, BK=8, 256 threads, 8x8 per thread.
// ---------------------------------------------------------------------------
__global__ __launch_bounds__(256) void k_gemm1(
    const float* __restrict__ X, const float* __restrict__ W, int N)
{
    __shared__ float As[8][128];
    __shared__ float Bs[8][128];

    const int bi  = blockIdx.x * 128;
    const int tid = threadIdx.x;
    const int tx  = tid & 15;   // 16 col-groups of 8
    const int ty  = tid >> 4;   // 16 row-groups of 8

    // X tile loader: 128 rows x 8 k = 1024 floats = 256 float4
    const int xr  = tid >> 1;          // 0..127
    const int xc4 = (tid & 1) * 4;     // 0 or 4
    // W tile loader: 8 k-rows x 128 cols = 256 float4
    const int wr  = tid >> 5;          // 0..7
    const int wc4 = (tid & 31) * 4;    // 0..124

    const int gr = bi + xr;

    float acc[8][8];
#pragma unroll
    for (int i = 0; i < 8; i++)
#pragma unroll
        for (int j = 0; j < 8; j++) acc[i][j] = 0.f;

    for (int k0 = 0; k0 < FIN; k0 += 8) {
        float4 xv = make_float4(0.f, 0.f, 0.f, 0.f);
        if (gr < N) xv = *(const float4*)&X[(size_t)gr * FIN + k0 + xc4];
        As[xc4 + 0][xr] = xv.x;
        As[xc4 + 1][xr] = xv.y;
        As[xc4 + 2][xr] = xv.z;
        As[xc4 + 3][xr] = xv.w;
        float4 wv = *(const float4*)&W[(size_t)(k0 + wr) * FHID + wc4];
        *(float4*)&Bs[wr][wc4] = wv;
        __syncthreads();

#pragma unroll
        for (int k = 0; k < 8; k++) {
            float a[8], b[8];
            *(float4*)&a[0] = *(const float4*)&As[k][ty * 8];
            *(float4*)&a[4] = *(const float4*)&As[k][ty * 8 + 4];
            *(float4*)&b[0] = *(const float4*)&Bs[k][tx * 8];
            *(float4*)&b[4] = *(const float4*)&Bs[k][tx * 8 + 4];
#pragma unroll
            for (int i = 0; i < 8; i++)
#pragma unroll
                for (int j = 0; j < 8; j++)
                    acc[i][j] = fmaf(a[i], b[j], acc[i][j]);
        }
        __syncthreads();
    }

#pragma unroll
    for (int i = 0; i < 8; i++) {
        int r = bi + ty * 8 + i;
        if (r < N) {
            float s = g_dinv[r];
#pragma unroll
            for (int j = 0; j < 8; j += 4) {
                float4 v;
                v.x = acc[i][j + 0] * s;
                v.y = acc[i][j + 1] * s;
                v.z = acc[i][j + 2] * s;
                v.w = acc[i][j + 3] * s;
                size_t off = (size_t)r * FHID + tx * 8 + j;
                *(float4*)&g_Hs[off] = v;
                *(float4*)&g_A[off]  = v;   // self-loop initialization
            }
        }
    }
}

// ---------------------------------------------------------------------------
// Scatter 128-feat: one warp per edge; red.global.add.v4.f32 (sm_90+).
// ---------------------------------------------------------------------------
__global__ __launch_bounds__(256) void k_scatter128(
    const int* __restrict__ row, const int* __restrict__ col, int E)
{
    long long t = (long long)blockIdx.x * (long long)blockDim.x + threadIdx.x;
    int e    = (int)(t >> 5);
    int lane = (int)(t & 31);
    if (e >= E) return;
    int r = __ldg(&row[e]);
    int c = __ldg(&col[e]);
    float4 v = *(const float4*)&g_Hs[(size_t)r * FHID + lane * 4];
    float* dst = &g_A[(size_t)c * FHID + lane * 4];
    asm volatile("red.global.add.v4.f32 [%0], {%1, %2, %3, %4};"
                 :: "l"(dst), "f"(v.x), "f"(v.y), "f"(v.z), "f"(v.w)
                 : "memory");
}

// ---------------------------------------------------------------------------
// GEMM2: H2 = relu(dinv*A + b1) (fused on load);  Hs2 = (H2 @ W2) * dinv;
// A2 initialized to Hs2. BM=128, BN=64, BK=8, 256 threads, 8x4 per thread.
// ---------------------------------------------------------------------------
__global__ __launch_bounds__(256) void k_gemm2(
    const float* __restrict__ W2, const float* __restrict__ b1, int N)
{
    __shared__ float As[8][128];
    __shared__ float Bs[8][64];

    const int bi  = blockIdx.x * 128;
    const int tid = threadIdx.x;
    const int tx  = tid & 15;   // 16 col-groups of 4 -> 64
    const int ty  = tid >> 4;   // 16 row-groups of 8 -> 128

    const int xr  = tid >> 1;
    const int xc4 = (tid & 1) * 4;
    const int wr  = tid >> 5;          // 0..7
    const int wc2 = (tid & 31) * 2;    // 0..62

    const int gr = bi + xr;
    const float dv = (gr < N) ? g_dinv[gr] : 0.f;

    float acc[8][4];
#pragma unroll
    for (int i = 0; i < 8; i++)
#pragma unroll
        for (int j = 0; j < 4; j++) acc[i][j] = 0.f;

    for (int k0 = 0; k0 < FHID; k0 += 8) {
        float4 av = make_float4(0.f, 0.f, 0.f, 0.f);
        if (gr < N) av = *(const float4*)&g_A[(size_t)gr * FHID + k0 + xc4];
        float4 bb = *(const float4*)&b1[k0 + xc4];
        As[xc4 + 0][xr] = fmaxf(fmaf(av.x, dv, bb.x), 0.f);
        As[xc4 + 1][xr] = fmaxf(fmaf(av.y, dv, bb.y), 0.f);
        As[xc4 + 2][xr] = fmaxf(fmaf(av.z, dv, bb.z), 0.f);
        As[xc4 + 3][xr] = fmaxf(fmaf(av.w, dv, bb.w), 0.f);
        float2 wv = *(const float2*)&W2[(size_t)(k0 + wr) * FOUT + wc2];
        Bs[wr][wc2 + 0] = wv.x;
        Bs[wr][wc2 + 1] = wv.y;
        __syncthreads();

#pragma unroll
        for (int k = 0; k < 8; k++) {
            float a[8], b[4];
            *(float4*)&a[0] = *(const float4*)&As[k][ty * 8];
            *(float4*)&a[4] = *(const float4*)&As[k][ty * 8 + 4];
            *(float4*)&b[0] = *(const float4*)&Bs[k][tx * 4];
#pragma unroll
            for (int i = 0; i < 8; i++)
#pragma unroll
                for (int j = 0; j < 4; j++)
                    acc[i][j] = fmaf(a[i], b[j], acc[i][j]);
        }
        __syncthreads();
    }

#pragma unroll
    for (int i = 0; i < 8; i++) {
        int r = bi + ty * 8 + i;
        if (r < N) {
            float s = g_dinv[r];
            float4 v;
            v.x = acc[i][0] * s;
            v.y = acc[i][1] * s;
            v.z = acc[i][2] * s;
            v.w = acc[i][3] * s;
            size_t off = (size_t)r * FOUT + tx * 4;
            *(float4*)&g_Hs2[off] = v;
            *(float4*)&g_A2[off]  = v;   // self-loop initialization
        }
    }
}

// ---------------------------------------------------------------------------
// Scatter 64-feat: half-warp per edge.
// ---------------------------------------------------------------------------
__global__ __launch_bounds__(256) void k_scatter64(
    const int* __restrict__ row, const int* __restrict__ col, int E)
{
    long long t = (long long)blockIdx.x * (long long)blockDim.x + threadIdx.x;
    int e    = (int)(t >> 4);
    int lane = (int)(t & 15);
    if (e >= E) return;
    int r = __ldg(&row[e]);
    int c = __ldg(&col[e]);
    float4 v = *(const float4*)&g_Hs2[(size_t)r * FOUT + lane * 4];
    float* dst = &g_A2[(size_t)c * FOUT + lane * 4];
    asm volatile("red.global.add.v4.f32 [%0], {%1, %2, %3, %4};"
                 :: "l"(dst), "f"(v.x), "f"(v.y), "f"(v.z), "f"(v.w)
                 : "memory");
}

// ---------------------------------------------------------------------------
// Final: out = dinv * A2 + b2   (no relu on layer 2)
// ---------------------------------------------------------------------------
__global__ void k_final(const float* __restrict__ b2, float* __restrict__ out, int N) {
    int t = blockIdx.x * blockDim.x + threadIdx.x;   // over N * 16 float4s
    if (t >= N * (FOUT / 4)) return;
    int r  = t >> 4;
    int c4 = (t & 15) * 4;
    float s = g_dinv[r];
    float4 a  = *(const float4*)&g_A2[(size_t)r * FOUT + c4];
    float4 bb = *(const float4*)&b2[c4];
    float4 o;
    o.x = fmaf(a.x, s, bb.x);
    o.y = fmaf(a.y, s, bb.y);
    o.z = fmaf(a.z, s, bb.z);
    o.w = fmaf(a.w, s, bb.w);
    *(float4*)&out[(size_t)r * FOUT + c4] = o;
}

// ---------------------------------------------------------------------------
// Launch
// ---------------------------------------------------------------------------
extern "C" void kernel_launch(void* const* d_in, const int* in_sizes, int n_in,
                              void* d_out, int out_size)
{
    const float* x  = (const float*)d_in[0];
    const int*   ei = (const int*)  d_in[1];
    const float* W1 = (const float*)d_in[2];
    const float* b1 = (const float*)d_in[3];
    const float* W2 = (const float*)d_in[4];
    const float* b2 = (const float*)d_in[5];
    float* out = (float*)d_out;

    const int N = in_sizes[0] / FIN;     // 100000
    const int E = in_sizes[1] / 2;       // 1600000
    const int* row = ei;       // sources
    const int* col = ei + E;   // targets

    k_init_dinv  <<<(N + 255) / 256, 256>>>(N);
    k_count_deg  <<<(E + 255) / 256, 256>>>(col, E);
    k_finish_dinv<<<(N + 255) / 256, 256>>>(N);

    k_gemm1<<<(N + 127) / 128, 256>>>(x, W1, N);

    long long t1 = (long long)E * 32LL;
    unsigned g1 = (unsigned)((t1 + 255) / 256);
    k_scatter128<<<g1, 256>>>(row, col, E);

    k_gemm2<<<(N + 127) / 128, 256>>>(W2, b1, N);

    long long t2 = (long long)E * 16LL;
    unsigned g2 = (unsigned)((t2 + 255) / 256);
    k_scatter64<<<g2, 256>>>(row, col, E);

    k_final<<<(N * (FOUT / 4) + 255) / 256, 256>>>(b2, out, N);
}

// round 3
// speedup vs baseline: 1.6400x; 1.6400x over previous
#include <cuda_runtime.h>
#include <cuda_bf16.h>
#include <cstdint>

// Problem constants (reference: N=100000, E=1600000, IN=HID=128, OUT=64)
#define NMAX 100000
#define FIN  128
#define FHID 128
#define FOUT 64
#define SCAN_BLK 1024

// ---------------------------------------------------------------------------
// Device-global scratch (no allocation allowed)
// ---------------------------------------------------------------------------
__device__ int   g_deg[NMAX];                 // target degree (without self-loop)
__device__ int   g_off[NMAX + 1];             // CSR offsets (exclusive scan of deg)
__device__ int   g_cursor[NMAX];              // placement cursors
__device__ int   g_bsum[128];                 // block sums for scan
__device__ float g_dinv[NMAX];                // rsqrt(deg+1)
__device__ int   g_eidx[1600000];             // CSR: source row per edge, grouped by col
__device__ float g_Hs [(size_t)NMAX * FHID];  // (X@W1) * dinv[row]
__device__ float g_H2 [(size_t)NMAX * FHID];  // relu(dinv*agg1 + b1)
__device__ float g_Hs2[(size_t)NMAX * FOUT];  // (H2@W2) * dinv[row]

// ---------------------------------------------------------------------------
// CSR build: degree count -> 3-pass scan -> placement; also dinv.
// ---------------------------------------------------------------------------
__global__ void k_zero_deg(int N) {
    int i = blockIdx.x * blockDim.x + threadIdx.x;
    if (i < N) g_deg[i] = 0;
}

__global__ void k_count(const int* __restrict__ col, int E) {
    int e = blockIdx.x * blockDim.x + threadIdx.x;
    if (e < E) atomicAdd(&g_deg[col[e]], 1);
}

// Pass 1: per-block inclusive scan of deg; writes exclusive partials + block sums.
__global__ __launch_bounds__(SCAN_BLK) void k_scan_block(int N) {
    __shared__ int s[SCAN_BLK];
    int t = threadIdx.x;
    int i = blockIdx.x * SCAN_BLK + t;
    int v = (i < N) ? g_deg[i] : 0;
    s[t] = v;
    __syncthreads();
#pragma unroll
    for (int d = 1; d < SCAN_BLK; d <<= 1) {
        int x = s[t];
        if (t >= d) x += s[t - d];
        __syncthreads();
        s[t] = x;
        __syncthreads();
    }
    if (i < N) g_off[i] = s[t] - v;              // exclusive partial
    if (t == SCAN_BLK - 1) g_bsum[blockIdx.x] = s[t];
}

// Pass 2: single block scans the (<=128) block sums, in place, exclusive.
__global__ __launch_bounds__(128) void k_scan_tops(int nb) {
    __shared__ int s[128];
    int t = threadIdx.x;
    int v = (t < nb) ? g_bsum[t] : 0;
    s[t] = v;
    __syncthreads();
#pragma unroll
    for (int d = 1; d < 128; d <<= 1) {
        int x = s[t];
        if (t >= d) x += s[t - d];
        __syncthreads();
        s[t] = x;
        __syncthreads();
    }
    if (t < nb) g_bsum[t] = s[t] - v;            // exclusive
}

// Pass 3: add block offsets; init cursors; compute dinv; close off[N].
__global__ void k_scan_add(int N, int E) {
    int i = blockIdx.x * blockDim.x + threadIdx.x;
    if (i < N) {
        int o = g_off[i] + g_bsum[i / SCAN_BLK];
        g_off[i]    = o;
        g_cursor[i] = o;
        g_dinv[i]   = rsqrtf((float)g_deg[i] + 1.0f);
    }
    if (i == 0) g_off[N] = E;
}

__global__ void k_place(const int* __restrict__ row, const int* __restrict__ col, int E) {
    int e = blockIdx.x * blockDim.x + threadIdx.x;
    if (e < E) {
        int c = col[e];
        int p = atomicAdd(&g_cursor[c], 1);
        g_eidx[p] = row[e];
    }
}

// ---------------------------------------------------------------------------
// GEMM1: Hs = (X @ W1) * dinv[row]
// BM=128, BN=128, BK=8, 256 threads, 8x8 per thread.
// ---------------------------------------------------------------------------
__global__ __launch_bounds__(256) void k_gemm1(
    const float* __restrict__ X, const float* __restrict__ W, int N)
{
    __shared__ float As[8][128];
    __shared__ float Bs[8][128];

    const int bi  = blockIdx.x * 128;
    const int tid = threadIdx.x;
    const int tx  = tid & 15;
    const int ty  = tid >> 4;

    const int xr  = tid >> 1;
    const int xc4 = (tid & 1) * 4;
    const int wr  = tid >> 5;
    const int wc4 = (tid & 31) * 4;

    const int gr = bi + xr;

    float acc[8][8];
#pragma unroll
    for (int i = 0; i < 8; i++)
#pragma unroll
        for (int j = 0; j < 8; j++) acc[i][j] = 0.f;

    for (int k0 = 0; k0 < FIN; k0 += 8) {
        float4 xv = make_float4(0.f, 0.f, 0.f, 0.f);
        if (gr < N) xv = *(const float4*)&X[(size_t)gr * FIN + k0 + xc4];
        As[xc4 + 0][xr] = xv.x;
        As[xc4 + 1][xr] = xv.y;
        As[xc4 + 2][xr] = xv.z;
        As[xc4 + 3][xr] = xv.w;
        float4 wv = *(const float4*)&W[(size_t)(k0 + wr) * FHID + wc4];
        *(float4*)&Bs[wr][wc4] = wv;
        __syncthreads();

#pragma unroll
        for (int k = 0; k < 8; k++) {
            float a[8], b[8];
            *(float4*)&a[0] = *(const float4*)&As[k][ty * 8];
            *(float4*)&a[4] = *(const float4*)&As[k][ty * 8 + 4];
            *(float4*)&b[0] = *(const float4*)&Bs[k][tx * 8];
            *(float4*)&b[4] = *(const float4*)&Bs[k][tx * 8 + 4];
#pragma unroll
            for (int i = 0; i < 8; i++)
#pragma unroll
                for (int j = 0; j < 8; j++)
                    acc[i][j] = fmaf(a[i], b[j], acc[i][j]);
        }
        __syncthreads();
    }

#pragma unroll
    for (int i = 0; i < 8; i++) {
        int r = bi + ty * 8 + i;
        if (r < N) {
            float s = g_dinv[r];
#pragma unroll
            for (int j = 0; j < 8; j += 4) {
                float4 v;
                v.x = acc[i][j + 0] * s;
                v.y = acc[i][j + 1] * s;
                v.z = acc[i][j + 2] * s;
                v.w = acc[i][j + 3] * s;
                *(float4*)&g_Hs[(size_t)r * FHID + tx * 8 + j] = v;
            }
        }
    }
}

// ---------------------------------------------------------------------------
// Agg1 (CSR gather): one warp per node, lane = float4 of 128 feats.
// acc = Hs[v] (self-loop) + sum_{edges->v} Hs[src]; H2 = relu(dinv[v]*acc + b1).
// ---------------------------------------------------------------------------
__global__ __launch_bounds__(256) void k_agg1(const float* __restrict__ b1, int N) {
    int w    = (blockIdx.x * blockDim.x + threadIdx.x) >> 5;
    int lane = threadIdx.x & 31;
    if (w >= N) return;
    const float4* Hs4 = (const float4*)g_Hs;
    int beg = g_off[w], end = g_off[w + 1];

    float4 acc = Hs4[(size_t)w * 32 + lane];      // self-loop term
    for (int j0 = beg; j0 < end; j0 += 32) {
        int jj = j0 + lane;
        int myidx = (jj < end) ? g_eidx[jj] : 0;
        int m = min(32, end - j0);
        for (int t = 0; t < m; t++) {
            int r = __shfl_sync(0xffffffffu, myidx, t);
            float4 v = Hs4[(size_t)r * 32 + lane];
            acc.x += v.x; acc.y += v.y; acc.z += v.z; acc.w += v.w;
        }
    }
    float s = g_dinv[w];
    float4 bb = ((const float4*)b1)[lane];
    float4 o;
    o.x = fmaxf(fmaf(acc.x, s, bb.x), 0.f);
    o.y = fmaxf(fmaf(acc.y, s, bb.y), 0.f);
    o.z = fmaxf(fmaf(acc.z, s, bb.z), 0.f);
    o.w = fmaxf(fmaf(acc.w, s, bb.w), 0.f);
    ((float4*)g_H2)[(size_t)w * 32 + lane] = o;
}

// ---------------------------------------------------------------------------
// GEMM2: Hs2 = (H2 @ W2) * dinv[row]
// BM=128, BN=64, BK=8, 256 threads, 8x4 per thread.
// ---------------------------------------------------------------------------
__global__ __launch_bounds__(256) void k_gemm2(
    const float* __restrict__ W2, int N)
{
    __shared__ float As[8][128];
    __shared__ float Bs[8][64];

    const int bi  = blockIdx.x * 128;
    const int tid = threadIdx.x;
    const int tx  = tid & 15;
    const int ty  = tid >> 4;

    const int xr  = tid >> 1;
    const int xc4 = (tid & 1) * 4;
    const int wr  = tid >> 5;
    const int wc2 = (tid & 31) * 2;

    const int gr = bi + xr;

    float acc[8][4];
#pragma unroll
    for (int i = 0; i < 8; i++)
#pragma unroll
        for (int j = 0; j < 4; j++) acc[i][j] = 0.f;

    for (int k0 = 0; k0 < FHID; k0 += 8) {
        float4 av = make_float4(0.f, 0.f, 0.f, 0.f);
        if (gr < N) av = *(const float4*)&g_H2[(size_t)gr * FHID + k0 + xc4];
        As[xc4 + 0][xr] = av.x;
        As[xc4 + 1][xr] = av.y;
        As[xc4 + 2][xr] = av.z;
        As[xc4 + 3][xr] = av.w;
        float2 wv = *(const float2*)&W2[(size_t)(k0 + wr) * FOUT + wc2];
        Bs[wr][wc2 + 0] = wv.x;
        Bs[wr][wc2 + 1] = wv.y;
        __syncthreads();

#pragma unroll
        for (int k = 0; k < 8; k++) {
            float a[8], b[4];
            *(float4*)&a[0] = *(const float4*)&As[k][ty * 8];
            *(float4*)&a[4] = *(const float4*)&As[k][ty * 8 + 4];
            *(float4*)&b[0] = *(const float4*)&Bs[k][tx * 4];
#pragma unroll
            for (int i = 0; i < 8; i++)
#pragma unroll
                for (int j = 0; j < 4; j++)
                    acc[i][j] = fmaf(a[i], b[j], acc[i][j]);
        }
        __syncthreads();
    }

#pragma unroll
    for (int i = 0; i < 8; i++) {
        int r = bi + ty * 8 + i;
        if (r < N) {
            float s = g_dinv[r];
            float4 v;
            v.x = acc[i][0] * s;
            v.y = acc[i][1] * s;
            v.z = acc[i][2] * s;
            v.w = acc[i][3] * s;
            *(float4*)&g_Hs2[(size_t)r * FOUT + tx * 4] = v;
        }
    }
}

// ---------------------------------------------------------------------------
// Agg2 (CSR gather): one warp per node, lane = float2 of 64 feats.
// out = dinv[v]*(Hs2[v] + sum Hs2[src]) + b2  -> writes d_out directly.
// ---------------------------------------------------------------------------
__global__ __launch_bounds__(256) void k_agg2(
    const float* __restrict__ b2, float* __restrict__ out, int N)
{
    int w    = (blockIdx.x * blockDim.x + threadIdx.x) >> 5;
    int lane = threadIdx.x & 31;
    if (w >= N) return;
    const float2* Hs2v = (const float2*)g_Hs2;
    int beg = g_off[w], end = g_off[w + 1];

    float2 acc = Hs2v[(size_t)w * 32 + lane];     // self-loop term
    for (int j0 = beg; j0 < end; j0 += 32) {
        int jj = j0 + lane;
        int myidx = (jj < end) ? g_eidx[jj] : 0;
        int m = min(32, end - j0);
        for (int t = 0; t < m; t++) {
            int r = __shfl_sync(0xffffffffu, myidx, t);
            float2 v = Hs2v[(size_t)r * 32 + lane];
            acc.x += v.x; acc.y += v.y;
        }
    }
    float s = g_dinv[w];
    float2 bb = ((const float2*)b2)[lane];
    float2 o;
    o.x = fmaf(acc.x, s, bb.x);
    o.y = fmaf(acc.y, s, bb.y);
    ((float2*)out)[(size_t)w * 32 + lane] = o;
}

// ---------------------------------------------------------------------------
// Launch
// ---------------------------------------------------------------------------
extern "C" void kernel_launch(void* const* d_in, const int* in_sizes, int n_in,
                              void* d_out, int out_size)
{
    const float* x  = (const float*)d_in[0];
    const int*   ei = (const int*)  d_in[1];
    const float* W1 = (const float*)d_in[2];
    const float* b1 = (const float*)d_in[3];
    const float* W2 = (const float*)d_in[4];
    const float* b2 = (const float*)d_in[5];
    float* out = (float*)d_out;

    const int N = in_sizes[0] / FIN;     // 100000
    const int E = in_sizes[1] / 2;       // 1600000
    const int* row = ei;       // sources
    const int* col = ei + E;   // targets

    const int nb = (N + SCAN_BLK - 1) / SCAN_BLK;   // 98

    // CSR build + dinv
    k_zero_deg  <<<(N + 255) / 256, 256>>>(N);
    k_count     <<<(E + 255) / 256, 256>>>(col, E);
    k_scan_block<<<nb, SCAN_BLK>>>(N);
    k_scan_tops <<<1, 128>>>(nb);
    k_scan_add  <<<(N + 255) / 256, 256>>>(N, E);
    k_place     <<<(E + 255) / 256, 256>>>(row, col, E);

    // Layer 1
    k_gemm1<<<(N + 127) / 128, 256>>>(x, W1, N);
    k_agg1 <<<(N * 32 + 255) / 256, 256>>>(b1, N);

    // Layer 2
    k_gemm2<<<(N + 127) / 128, 256>>>(W2, N);
    k_agg2 <<<(N * 32 + 255) / 256, 256>>>(b2, out, N);
}